// round 2
// baseline (speedup 1.0000x reference)
#include <cuda_runtime.h>
#include <math.h>

#define DIM   1024
#define VOCAB 50257
#define G     148          // one CTA per SM; wave-1 placement is deterministic
#define NROW  7            // ceil(1024/148)

__device__ float g_yk[DIM];
__device__ float g_z[DIM];
__device__ unsigned int g_bar1;   // zero-initialized; reset at end of each launch
__device__ unsigned int g_bar2;

__global__ void __launch_bounds__(1024, 1)
fused_kernel(const float* __restrict__ filters,
             const float* __restrict__ w_t,
             const float* __restrict__ w_h,
             float* __restrict__ out)
{
    const int tid = threadIdx.x;
    const int bid = blockIdx.x;
    const int warp = tid >> 5, lane = tid & 31;

    __shared__ float s_y[DIM];
    __shared__ float sp[32][14];    // per-warp partials for 14 dots
    __shared__ float res[14];       // final dot results for this block's rows
    __shared__ float sred[32];      // softmax reductions

    // ---------------- Phase 1: distributed gather of y_k ----------------
    // Element j handled by block (j % G); each block gathers <= 7 elements.
    if (tid < NROW) {
        int j = bid + tid * G;
        if (j < DIM) {
            float v = filters[(size_t)j * VOCAB];
            g_yk[j] = (j == DIM - 1) ? v : fmaxf(v, 0.0f);
        }
    }
    __threadfence();
    __syncthreads();
    if (tid == 0) {
        atomicAdd(&g_bar1, 1u);
        while (atomicAdd(&g_bar1, 0u) < G) { }
    }
    __syncthreads();

    // Load full y into shared (bypass L1 for cross-SM visibility).
    s_y[tid] = __ldcg(&g_yk[tid]);
    __syncthreads();

    // ---------------- Phase 2: matvec (rows r = bid + i*G) ----------------
    const float y = s_y[tid];
    float p[2 * NROW];
    #pragma unroll
    for (int i = 0; i < NROW; i++) {
        int r = bid + i * G;
        float pt = 0.0f, ph = 0.0f;
        if (r < DIM) {
            pt = w_t[(size_t)r * DIM + tid] * y;
            ph = w_h[(size_t)r * DIM + tid] * y;
        }
        p[2 * i]     = pt;
        p[2 * i + 1] = ph;
    }

    // Warp-level reduce all 14 partials.
    #pragma unroll
    for (int d = 0; d < 2 * NROW; d++) {
        float v = p[d];
        #pragma unroll
        for (int o = 16; o; o >>= 1) v += __shfl_xor_sync(0xffffffffu, v, o);
        if (lane == 0) sp[warp][d] = v;
    }
    __syncthreads();

    // Second level: warp d (d < 14) reduces dot d across the 32 warp-partials.
    if (warp < 2 * NROW) {
        float v = sp[lane][warp];
        #pragma unroll
        for (int o = 16; o; o >>= 1) v += __shfl_xor_sync(0xffffffffu, v, o);
        if (lane == 0) res[warp] = v;
    }
    __syncthreads();

    // Threads 0..6 finalize their row's z.
    if (tid < NROW) {
        int r = bid + tid * G;
        if (r < DIM) {
            float T = res[2 * tid];
            float H = res[2 * tid + 1];
            float t = 1.0f / (1.0f + expf(-T));
            float g = fmaxf(H, 0.0f);
            float yk = s_y[r];
            g_z[r] = t * g + (1.0f - t) * yk;
        }
    }
    __threadfence();
    __syncthreads();

    // ---------------- Arrive-only barrier 2; only block 0 waits ----------------
    if (tid == 0) atomicAdd(&g_bar2, 1u);
    if (bid != 0) return;

    if (tid == 0) {
        while (atomicAdd(&g_bar2, 0u) < G) { }
    }
    __syncthreads();

    // ---------------- Phase 3: log-softmax on block 0 ----------------
    float z = __ldcg(&g_z[tid]);

    // max reduce
    float m = z;
    #pragma unroll
    for (int o = 16; o; o >>= 1) m = fmaxf(m, __shfl_xor_sync(0xffffffffu, m, o));
    if (lane == 0) sred[warp] = m;
    __syncthreads();
    if (warp == 0) {
        float v = sred[lane];
        #pragma unroll
        for (int o = 16; o; o >>= 1) v = fmaxf(v, __shfl_xor_sync(0xffffffffu, v, o));
        if (lane == 0) sred[0] = v;
    }
    __syncthreads();
    const float gmax = sred[0];
    __syncthreads();

    // sum of exp reduce
    float s = expf(z - gmax);
    #pragma unroll
    for (int o = 16; o; o >>= 1) s += __shfl_xor_sync(0xffffffffu, s, o);
    if (lane == 0) sred[warp] = s;
    __syncthreads();
    if (warp == 0) {
        float v = sred[lane];
        #pragma unroll
        for (int o = 16; o; o >>= 1) v += __shfl_xor_sync(0xffffffffu, v, o);
        if (lane == 0) sred[0] = v;
    }
    __syncthreads();

    out[tid] = z - gmax - logf(sred[0]);

    // Reset barrier state for the next graph replay (launches are stream-ordered).
    __syncthreads();
    if (tid == 0) { g_bar1 = 0u; g_bar2 = 0u; }
}

extern "C" void kernel_launch(void* const* d_in, const int* in_sizes, int n_in,
                              void* d_out, int out_size) {
    // metadata order: input (int32, unused), filters, w_t, w_h
    const float* filters = (const float*)d_in[1];
    const float* w_t     = (const float*)d_in[2];
    const float* w_h     = (const float*)d_in[3];
    float* out           = (float*)d_out;

    fused_kernel<<<G, 1024>>>(filters, w_t, w_h, out);
}

// round 3
// speedup vs baseline: 1.1879x; 1.1879x over previous
#include <cuda_runtime.h>
#include <math.h>

#define DIM   1024
#define VOCAB 50257
#define G     148      // one wave: one CTA per SM
#define NROW  7        // rows per block: 148*7 = 1036 >= 1024

__device__ float g_z[DIM];
__device__ unsigned int g_bar;   // zero-init; reset by block 0 each launch

__global__ void __launch_bounds__(1024, 1)
fused_kernel(const float* __restrict__ filters,
             const float* __restrict__ w_t,
             const float* __restrict__ w_h,
             float* __restrict__ out)
{
    const int tid  = threadIdx.x;
    const int bid  = blockIdx.x;
    const int warp = tid >> 5, lane = tid & 31;

    __shared__ float s_y[DIM];
    __shared__ float part[14][2];   // [combo][half] partial sums
    __shared__ float sred[32];

    // --- Warp work assignment: warp w < 28 handles combo c = w/2, half = w&1.
    // combo c: row i = c>>1 (0..6), matrix = c&1 (0 = w_t, 1 = w_h).
    const int c    = warp >> 1;
    const int half = warp & 1;
    const int i    = c >> 1;
    const int mat  = c & 1;
    const int row  = bid * NROW + i;
    const bool active = (warp < 28) && (row < DIM);

    // ---- Issue weight loads FIRST (their DRAM latency overlaps the gather) ----
    float4 wv[4];
    if (active) {
        const float* W = mat ? w_h : w_t;
        const float4* Wrow = (const float4*)(W + (size_t)row * DIM);
        #pragma unroll
        for (int k = 0; k < 4; k++)
            wv[k] = Wrow[half * 128 + k * 32 + lane];
    }

    // ---- Redundant per-block gather of y (no global barrier needed) ----
    {
        float v = filters[(size_t)tid * VOCAB];
        s_y[tid] = (tid == DIM - 1) ? v : fmaxf(v, 0.0f);
    }
    __syncthreads();

    // ---- Half-dot: 512 elements per warp ----
    if (active) {
        const float4* y4 = (const float4*)s_y;
        float acc = 0.0f;
        #pragma unroll
        for (int k = 0; k < 4; k++) {
            float4 yv = y4[half * 128 + k * 32 + lane];
            acc += wv[k].x * yv.x + wv[k].y * yv.y + wv[k].z * yv.z + wv[k].w * yv.w;
        }
        #pragma unroll
        for (int o = 16; o; o >>= 1) acc += __shfl_xor_sync(0xffffffffu, acc, o);
        if (lane == 0) part[c][half] = acc;
    }
    __syncthreads();

    // ---- Finalize z for this block's rows ----
    if (tid < NROW) {
        int r = bid * NROW + tid;
        if (r < DIM) {
            float T = part[2 * tid][0]     + part[2 * tid][1];
            float H = part[2 * tid + 1][0] + part[2 * tid + 1][1];
            float t = 1.0f / (1.0f + expf(-T));
            float g = fmaxf(H, 0.0f);
            float yk = s_y[r];
            __stcg(&g_z[r], t * g + (1.0f - t) * yk);
        }
    }
    __threadfence();   // release z stores
    __syncthreads();

    // ---- Arrive (REDG, no return). Only block 0 waits. ----
    if (tid == 0) atomicAdd(&g_bar, 1u);
    if (bid != 0) return;

    if (tid == 0) {
        volatile unsigned int* bar = &g_bar;
        while (*bar < G) { }
        __threadfence();   // acquire
    }
    __syncthreads();

    // ---- log-softmax on block 0 ----
    float z = __ldcg(&g_z[tid]);

    float m = z;
    #pragma unroll
    for (int o = 16; o; o >>= 1) m = fmaxf(m, __shfl_xor_sync(0xffffffffu, m, o));
    if (lane == 0) sred[warp] = m;
    __syncthreads();
    if (warp == 0) {
        float v = sred[lane];
        #pragma unroll
        for (int o = 16; o; o >>= 1) v = fmaxf(v, __shfl_xor_sync(0xffffffffu, v, o));
        if (lane == 0) sred[0] = v;
    }
    __syncthreads();
    const float gmax = sred[0];
    __syncthreads();

    float s = expf(z - gmax);
    #pragma unroll
    for (int o = 16; o; o >>= 1) s += __shfl_xor_sync(0xffffffffu, s, o);
    if (lane == 0) sred[warp] = s;
    __syncthreads();
    if (warp == 0) {
        float v = sred[lane];
        #pragma unroll
        for (int o = 16; o; o >>= 1) v += __shfl_xor_sync(0xffffffffu, v, o);
        if (lane == 0) sred[0] = v;
    }
    __syncthreads();

    out[tid] = z - gmax - logf(sred[0]);

    __syncthreads();
    if (tid == 0) g_bar = 0u;   // reset for next graph replay
}

extern "C" void kernel_launch(void* const* d_in, const int* in_sizes, int n_in,
                              void* d_out, int out_size) {
    // metadata order: input (int32, unused), filters, w_t, w_h
    const float* filters = (const float*)d_in[1];
    const float* w_t     = (const float*)d_in[2];
    const float* w_h     = (const float*)d_in[3];
    float* out           = (float*)d_out;

    fused_kernel<<<G, 1024>>>(filters, w_t, w_h, out);
}

// round 4
// speedup vs baseline: 1.1922x; 1.0036x over previous
#include <cuda_runtime.h>
#include <math.h>

#define DIM   1024
#define VOCAB 50257
#define G     148
#define NROW  7        // rows per block: 148*7 = 1036 >= 1024

__device__ float g_yk[DIM];
__device__ float g_z[DIM];
__device__ unsigned int g_bar;   // zero-init; reset by block 0 each launch

// ---------------- K1: distributed gather of filters[:,0] ----------------
__global__ void yk_kernel(const float* __restrict__ filters) {
    int j = blockIdx.x * 32 + threadIdx.x;   // 32 blocks x 32 threads = 1024
    float v = filters[(size_t)j * VOCAB];
    g_yk[j] = (j == DIM - 1) ? v : fmaxf(v, 0.0f);
}

// ---------------- K2: matvec + gate + barrier + softmax ----------------
__global__ void __launch_bounds__(512, 1)
main_kernel(const float* __restrict__ w_t,
            const float* __restrict__ w_h,
            float* __restrict__ out)
{
    const int tid  = threadIdx.x;
    const int bid  = blockIdx.x;
    const int warp = tid >> 5, lane = tid & 31;

    __shared__ float s_y[DIM];
    __shared__ float part[14];
    __shared__ float sred[16];

    // warp w < 14: row i = w>>1 (0..6), matrix = w&1 (0=w_t, 1=w_h).
    const int i   = warp >> 1;
    const int mat = warp & 1;
    const int row = bid * NROW + i;
    const bool active = (warp < 14) && (row < DIM);

    // Issue full-row weight loads BEFORE the grid dependency sync:
    // they are independent of K1's output and overlap its execution (PDL).
    float4 wv[8];
    if (active) {
        const float* W = mat ? w_h : w_t;
        const float4* Wrow = (const float4*)(W + (size_t)row * DIM);
        #pragma unroll
        for (int k = 0; k < 8; k++)
            wv[k] = Wrow[k * 32 + lane];
    }

    cudaGridDependencySynchronize();   // wait for yk_kernel's writes

    // Compact y: 4 KB contiguous, L2-hot.
    if (tid < 256)
        ((float4*)s_y)[tid] = ((const float4*)g_yk)[tid];
    __syncthreads();

    if (active) {
        const float4* y4 = (const float4*)s_y;
        float a0 = 0.0f, a1 = 0.0f;
        #pragma unroll
        for (int k = 0; k < 8; k += 2) {
            float4 y0 = y4[k * 32 + lane];
            float4 y1 = y4[(k + 1) * 32 + lane];
            a0 += wv[k].x * y0.x + wv[k].y * y0.y + wv[k].z * y0.z + wv[k].w * y0.w;
            a1 += wv[k+1].x * y1.x + wv[k+1].y * y1.y + wv[k+1].z * y1.z + wv[k+1].w * y1.w;
        }
        float acc = a0 + a1;
        #pragma unroll
        for (int o = 16; o; o >>= 1) acc += __shfl_xor_sync(0xffffffffu, acc, o);
        if (lane == 0) part[warp] = acc;
    }
    __syncthreads();

    if (tid < NROW) {
        int r = bid * NROW + tid;
        if (r < DIM) {
            float T = part[2 * tid];
            float H = part[2 * tid + 1];
            float t = 1.0f / (1.0f + __expf(-T));
            float g = fmaxf(H, 0.0f);
            float yk = s_y[r];
            __stcg(&g_z[r], t * g + (1.0f - t) * yk);
        }
    }
    __threadfence();
    __syncthreads();

    if (tid == 0) atomicAdd(&g_bar, 1u);
    if (bid != 0) return;

    if (tid == 0) {
        volatile unsigned int* bar = &g_bar;
        while (*bar < G) { }
        __threadfence();
    }
    __syncthreads();

    // ---- log-softmax on block 0 (512 threads, 2 elements each) ----
    float z0 = __ldcg(&g_z[tid]);
    float z1 = __ldcg(&g_z[tid + 512]);

    float m = fmaxf(z0, z1);
    #pragma unroll
    for (int o = 16; o; o >>= 1) m = fmaxf(m, __shfl_xor_sync(0xffffffffu, m, o));
    if (lane == 0) sred[warp] = m;
    __syncthreads();
    if (warp == 0) {
        float v = (lane < 16) ? sred[lane] : -1e30f;
        #pragma unroll
        for (int o = 8; o; o >>= 1) v = fmaxf(v, __shfl_xor_sync(0xffffffffu, v, o));
        if (lane == 0) sred[0] = v;
    }
    __syncthreads();
    const float gmax = sred[0];
    __syncthreads();

    float s = __expf(z0 - gmax) + __expf(z1 - gmax);
    #pragma unroll
    for (int o = 16; o; o >>= 1) s += __shfl_xor_sync(0xffffffffu, s, o);
    if (lane == 0) sred[warp] = s;
    __syncthreads();
    if (warp == 0) {
        float v = (lane < 16) ? sred[lane] : 0.0f;
        #pragma unroll
        for (int o = 8; o; o >>= 1) v += __shfl_xor_sync(0xffffffffu, v, o);
        if (lane == 0) sred[0] = v;
    }
    __syncthreads();

    const float lse = gmax + logf(sred[0]);
    out[tid]       = z0 - lse;
    out[tid + 512] = z1 - lse;

    __syncthreads();
    if (tid == 0) g_bar = 0u;   // reset for next graph replay
}

extern "C" void kernel_launch(void* const* d_in, const int* in_sizes, int n_in,
                              void* d_out, int out_size) {
    // metadata order: input (int32, unused), filters, w_t, w_h
    const float* filters = (const float*)d_in[1];
    const float* w_t     = (const float*)d_in[2];
    const float* w_h     = (const float*)d_in[3];
    float* out           = (float*)d_out;

    yk_kernel<<<32, 32>>>(filters);

    // Launch K2 with programmatic stream serialization so its prologue
    // (launch ramp + weight loads) overlaps K1.
    cudaLaunchConfig_t cfg = {};
    cfg.gridDim  = dim3(G, 1, 1);
    cfg.blockDim = dim3(512, 1, 1);
    cfg.dynamicSmemBytes = 0;
    cfg.stream = 0;
    cudaLaunchAttribute attrs[1];
    attrs[0].id = cudaLaunchAttributeProgrammaticStreamSerialization;
    attrs[0].val.programmaticStreamSerializationAllowed = 1;
    cfg.attrs = attrs;
    cfg.numAttrs = 1;
    cudaLaunchKernelEx(&cfg, main_kernel, w_t, w_h, out);
}